// round 2
// baseline (speedup 1.0000x reference)
#include <cuda_runtime.h>

#define N_NODES  50000
#define N_EDGES  800000
#define E_TOT    (N_EDGES + N_NODES)   // 850000 (edges + self loops)
#define HIDDEN   128
#define N_GRAPHS 512
#define NCHUNK   ((N_NODES + 255) / 256)   // 196

// ---------------- scratch (static device memory; no allocs) ----------------
__device__ float g_xl[(size_t)N_NODES * HIDDEN];
__device__ float g_xr[(size_t)N_NODES * HIDDEN];
__device__ float g_h [(size_t)N_NODES * HIDDEN];
__device__ int   g_cnt[N_NODES];
__device__ int   g_tmp[N_NODES];
__device__ int   g_off[N_NODES + 1];
__device__ int   g_cursor[N_NODES];
__device__ int   g_srcs[E_TOT];
__device__ int   g_chunksum[NCHUNK];
__device__ int   g_chunkoff[NCHUNK];
__device__ float g_gsum[N_GRAPHS * HIDDEN];
__device__ float g_gcnt[N_GRAPHS];
__device__ int   g_is64_ei;     // 1 if edge_index buffer is int64, 0 if int32
__device__ int   g_is64_batch;  // same for batch

// ---------------- dtype detection ----------------
// int64 values here are small positives -> every odd 32-bit word (high half) is 0.
// int32 data -> sampled odd words are node/graph ids, nonzero w.h.p. over 64 samples.
__global__ void k_detect(const int* __restrict__ ei_raw,
                         const int* __restrict__ batch_raw) {
    if (blockIdx.x == 0 && threadIdx.x == 0) {
        int nz = 0;
        for (int i = 0; i < 64; ++i) {
            int w = 2 * (i * 12000) + 1;          // < 1,512,002 : safe for both dtypes
            nz |= ei_raw[w];
        }
        g_is64_ei = (nz == 0) ? 1 : 0;
        int nzb = 0;
        for (int i = 0; i < 64; ++i) {
            int w = 2 * (i * 390) + 1;            // < 49,922 : safe for both dtypes
            nzb |= batch_raw[w];
        }
        g_is64_batch = (nzb == 0) ? 1 : 0;
    }
}

__device__ __forceinline__ int load_idx(const void* p, long long i, int is64) {
    return is64 ? (int)((const long long*)p)[i] : ((const int*)p)[i];
}
__device__ __forceinline__ int clampi(int v, int lo, int hi) {
    return v < lo ? lo : (v > hi ? hi : v);
}

// ---------------- CSR build ----------------
__global__ void k_zero_cnt() {
    int i = blockIdx.x * blockDim.x + threadIdx.x;
    if (i < N_NODES) g_cnt[i] = 0;
}

__global__ void k_count(const void* __restrict__ ei) {
    int e = blockIdx.x * blockDim.x + threadIdx.x;
    if (e >= E_TOT) return;
    int is64 = g_is64_ei;
    int dst = (e < N_EDGES) ? load_idx(ei, (long long)N_EDGES + e, is64)
                            : (e - N_EDGES);
    dst = clampi(dst, 0, N_NODES - 1);
    atomicAdd(&g_cnt[dst], 1);
}

__global__ void k_scan1() {
    __shared__ int sm[256];
    int i = blockIdx.x * 256 + threadIdx.x;
    int v = (i < N_NODES) ? g_cnt[i] : 0;
    sm[threadIdx.x] = v;
    __syncthreads();
    #pragma unroll
    for (int d = 1; d < 256; d <<= 1) {
        int t = (threadIdx.x >= d) ? sm[threadIdx.x - d] : 0;
        __syncthreads();
        sm[threadIdx.x] += t;
        __syncthreads();
    }
    if (i < N_NODES) g_tmp[i] = sm[threadIdx.x];
    if (threadIdx.x == 255) g_chunksum[blockIdx.x] = sm[255];
}

__global__ void k_scan2() {
    __shared__ int sm[256];
    int t = threadIdx.x;
    int v = (t < NCHUNK) ? g_chunksum[t] : 0;
    sm[t] = v;
    __syncthreads();
    #pragma unroll
    for (int d = 1; d < 256; d <<= 1) {
        int u = (t >= d) ? sm[t - d] : 0;
        __syncthreads();
        sm[t] += u;
        __syncthreads();
    }
    if (t < NCHUNK) g_chunkoff[t] = sm[t] - v;   // exclusive scan of chunk sums
}

__global__ void k_scan3() {
    int i = blockIdx.x * 256 + threadIdx.x;
    if (i < N_NODES) {
        int v = g_tmp[i] + g_chunkoff[blockIdx.x];   // inclusive prefix
        g_off[i + 1]  = v;
        g_cursor[i]   = v - g_cnt[i];                // exclusive prefix
    }
    if (i == 0) g_off[0] = 0;
}

__global__ void k_scatter(const void* __restrict__ ei) {
    int e = blockIdx.x * blockDim.x + threadIdx.x;
    if (e >= E_TOT) return;
    int is64 = g_is64_ei;
    int src, dst;
    if (e < N_EDGES) {
        src = load_idx(ei, e, is64);
        dst = load_idx(ei, (long long)N_EDGES + e, is64);
    } else {
        src = e - N_EDGES; dst = src;
    }
    src = clampi(src, 0, N_NODES - 1);
    dst = clampi(dst, 0, N_NODES - 1);
    int slot = atomicAdd(&g_cursor[dst], 1);
    if (slot >= 0 && slot < E_TOT) g_srcs[slot] = src;
}

// ---------------- fused xl/xr GEMM: out = A @ W + b ----------------
// blockIdx.y = 0 -> (Wl, bl, g_xl); 1 -> (Wr, br, g_xr)
__global__ __launch_bounds__(256, 2) void k_gemm(
    const float* __restrict__ x_ext, int use_h, int K,
    const float* __restrict__ Wl, const float* __restrict__ bl,
    const float* __restrict__ Wr, const float* __restrict__ br)
{
    const float* A    = use_h ? g_h : x_ext;
    const float* W    = blockIdx.y ? Wr : Wl;
    const float* bias = blockIdx.y ? br : bl;
    float*       out  = blockIdx.y ? g_xr : g_xl;

    __shared__ float As[128][32];
    __shared__ float Ws[32][128];

    int row0 = blockIdx.x * 128;
    int t  = threadIdx.x;
    int tx = t & 15, ty = t >> 4;

    float acc[8][8];
    #pragma unroll
    for (int i = 0; i < 8; ++i)
        #pragma unroll
        for (int j = 0; j < 8; ++j) acc[i][j] = 0.f;

    for (int k0 = 0; k0 < K; k0 += 32) {
        #pragma unroll
        for (int l = 0; l < 4; ++l) {            // A tile: 128x32 floats
            int idx = t + l * 256;               // float4 index 0..1023
            int r = idx >> 3;
            int c = (idx & 7) << 2;
            float4 v = make_float4(0.f, 0.f, 0.f, 0.f);
            int row = row0 + r;
            if (row < N_NODES)
                v = *(const float4*)(A + (size_t)row * K + k0 + c);
            *(float4*)&As[r][c] = v;
        }
        #pragma unroll
        for (int l = 0; l < 4; ++l) {            // W tile: 32x128 floats
            int idx = t + l * 256;
            int r = idx >> 5;
            int c = (idx & 31) << 2;
            *(float4*)&Ws[r][c] = *(const float4*)(W + (size_t)(k0 + r) * HIDDEN + c);
        }
        __syncthreads();
        #pragma unroll
        for (int kk = 0; kk < 32; ++kk) {
            float a[8], w[8];
            #pragma unroll
            for (int i = 0; i < 8; ++i) a[i] = As[ty * 8 + i][kk];
            *(float4*)&w[0] = *(const float4*)&Ws[kk][tx * 8];
            *(float4*)&w[4] = *(const float4*)&Ws[kk][tx * 8 + 4];
            #pragma unroll
            for (int i = 0; i < 8; ++i)
                #pragma unroll
                for (int j = 0; j < 8; ++j)
                    acc[i][j] = fmaf(a[i], w[j], acc[i][j]);
        }
        __syncthreads();
    }

    float bv[8];
    *(float4*)&bv[0] = *(const float4*)(bias + tx * 8);
    *(float4*)&bv[4] = *(const float4*)(bias + tx * 8 + 4);
    #pragma unroll
    for (int i = 0; i < 8; ++i) {
        int row = row0 + ty * 8 + i;
        if (row < N_NODES) {
            float4 o0 = make_float4(acc[i][0] + bv[0], acc[i][1] + bv[1],
                                    acc[i][2] + bv[2], acc[i][3] + bv[3]);
            float4 o1 = make_float4(acc[i][4] + bv[4], acc[i][5] + bv[5],
                                    acc[i][6] + bv[6], acc[i][7] + bv[7]);
            *(float4*)(out + (size_t)row * HIDDEN + tx * 8)     = o0;
            *(float4*)(out + (size_t)row * HIDDEN + tx * 8 + 4) = o1;
        }
    }
}

// ---------------- edge phase: warp-per-dst online softmax + aggregate ----------------
__device__ __forceinline__ float lrelu(float v) { return v > 0.f ? v : 0.2f * v; }

__global__ __launch_bounds__(256) void k_edge(const float* __restrict__ att,
                                              const float* __restrict__ bias)
{
    int warp = (blockIdx.x * blockDim.x + threadIdx.x) >> 5;
    int lane = threadIdx.x & 31;
    if (warp >= N_NODES) return;

    const float4* xl4 = (const float4*)g_xl;
    float4 a4 = ((const float4*)att)[lane];
    float4 r4 = ((const float4*)g_xr)[(size_t)warp * 32 + lane];

    int beg = g_off[warp], end = g_off[warp + 1];
    float  m = -1e30f, s = 0.f;
    float4 acc = make_float4(0.f, 0.f, 0.f, 0.f);

    for (int p = beg; p < end; ++p) {
        int src = g_srcs[p];
        float4 v = xl4[(size_t)src * 32 + lane];
        float e = lrelu(v.x + r4.x) * a4.x
                + lrelu(v.y + r4.y) * a4.y
                + lrelu(v.z + r4.z) * a4.z
                + lrelu(v.w + r4.w) * a4.w;
        #pragma unroll
        for (int o = 16; o; o >>= 1) e += __shfl_xor_sync(0xffffffffu, e, o);

        if (e <= m) {                         // warp-uniform branch
            float q = __expf(e - m);
            s += q;
            acc.x = fmaf(q, v.x, acc.x);
            acc.y = fmaf(q, v.y, acc.y);
            acc.z = fmaf(q, v.z, acc.z);
            acc.w = fmaf(q, v.w, acc.w);
        } else {
            float c = __expf(m - e);          // first iter: expf(-huge) = 0
            s = fmaf(s, c, 1.f);
            acc.x = fmaf(acc.x, c, v.x);
            acc.y = fmaf(acc.y, c, v.y);
            acc.z = fmaf(acc.z, c, v.z);
            acc.w = fmaf(acc.w, c, v.w);
            m = e;
        }
    }

    float inv = 1.f / (s + 1e-16f);
    float4 b4 = ((const float4*)bias)[lane];
    float4 o;
    o.x = fmaxf(fmaf(acc.x, inv, b4.x), 0.f);
    o.y = fmaxf(fmaf(acc.y, inv, b4.y), 0.f);
    o.z = fmaxf(fmaf(acc.z, inv, b4.z), 0.f);
    o.w = fmaxf(fmaf(acc.w, inv, b4.w), 0.f);
    ((float4*)g_h)[(size_t)warp * 32 + lane] = o;
}

// ---------------- pooling + head MLP ----------------
__global__ void k_zero_pool() {
    int i = blockIdx.x * blockDim.x + threadIdx.x;
    if (i < N_GRAPHS * HIDDEN) g_gsum[i] = 0.f;
    if (i < N_GRAPHS)          g_gcnt[i] = 0.f;
}

__global__ __launch_bounds__(256) void k_pool(const void* __restrict__ batch) {
    int warp = (blockIdx.x * blockDim.x + threadIdx.x) >> 5;
    int lane = threadIdx.x & 31;
    if (warp >= N_NODES) return;
    int g = load_idx(batch, warp, g_is64_batch);
    g = clampi(g, 0, N_GRAPHS - 1);
    float4 h = ((const float4*)g_h)[(size_t)warp * 32 + lane];
    float* base = &g_gsum[g * HIDDEN + lane * 4];
    atomicAdd(base + 0, h.x);
    atomicAdd(base + 1, h.y);
    atomicAdd(base + 2, h.z);
    atomicAdd(base + 3, h.w);
    if (lane == 0) atomicAdd(&g_gcnt[g], 1.f);
}

__global__ void k_final(const float* __restrict__ lin_w, const float* __restrict__ lin_b,
                        const float* __restrict__ out_w, const float* __restrict__ out_b,
                        float* __restrict__ out)
{
    int g = blockIdx.x;
    int t = threadIdx.x;          // 128 threads
    __shared__ float gm[128];
    __shared__ float hh[64];
    float cnt = fmaxf(g_gcnt[g], 1.f);
    gm[t] = g_gsum[g * HIDDEN + t] / cnt;
    __syncthreads();
    if (t < 64) {
        float acc = lin_b[t];
        #pragma unroll 8
        for (int k = 0; k < 128; ++k) acc = fmaf(gm[k], lin_w[k * 64 + t], acc);
        hh[t] = fmaxf(acc, 0.f) * out_w[t];
    }
    __syncthreads();
    if (t == 0) {
        float acc = out_b[0];
        #pragma unroll 8
        for (int k = 0; k < 64; ++k) acc += hh[k];
        out[g] = acc;
    }
}

// ---------------- launch ----------------
extern "C" void kernel_launch(void* const* d_in, const int* in_sizes, int n_in,
                              void* d_out, int out_size)
{
    const float* x     = (const float*)d_in[0];
    const void*  ei    = d_in[1];
    const void*  batch = d_in[2];
    const float* Wl[3]  = {(const float*)d_in[3],  (const float*)d_in[9],  (const float*)d_in[15]};
    const float* bl[3]  = {(const float*)d_in[4],  (const float*)d_in[10], (const float*)d_in[16]};
    const float* Wr[3]  = {(const float*)d_in[5],  (const float*)d_in[11], (const float*)d_in[17]};
    const float* br[3]  = {(const float*)d_in[6],  (const float*)d_in[12], (const float*)d_in[18]};
    const float* att[3] = {(const float*)d_in[7],  (const float*)d_in[13], (const float*)d_in[19]};
    const float* bb[3]  = {(const float*)d_in[8],  (const float*)d_in[14], (const float*)d_in[20]};
    const float* lin_w  = (const float*)d_in[21];
    const float* lin_b  = (const float*)d_in[22];
    const float* out_w  = (const float*)d_in[23];
    const float* out_b  = (const float*)d_in[24];
    float* out = (float*)d_out;

    // dtype of integer inputs (int32 vs int64) decided on-device, deterministically
    k_detect<<<1, 32>>>((const int*)ei, (const int*)batch);

    // CSR (dst-sorted) built every call
    k_zero_cnt<<<(N_NODES + 255) / 256, 256>>>();
    k_count   <<<(E_TOT   + 255) / 256, 256>>>(ei);
    k_scan1   <<<NCHUNK, 256>>>();
    k_scan2   <<<1, 256>>>();
    k_scan3   <<<NCHUNK, 256>>>();
    k_scatter <<<(E_TOT   + 255) / 256, 256>>>(ei);

    for (int L = 0; L < 3; ++L) {
        int K = (L == 0) ? 64 : HIDDEN;
        dim3 grid((N_NODES + 127) / 128, 2);
        k_gemm<<<grid, 256>>>(x, L > 0 ? 1 : 0, K, Wl[L], bl[L], Wr[L], br[L]);
        k_edge<<<(N_NODES * 32 + 255) / 256, 256>>>(att[L], bb[L]);
    }

    k_zero_pool<<<(N_GRAPHS * HIDDEN + 255) / 256, 256>>>();
    k_pool     <<<(N_NODES * 32 + 255) / 256, 256>>>(batch);
    k_final    <<<N_GRAPHS, 128>>>(lin_w, lin_b, out_w, out_b, out);
}

// round 3
// speedup vs baseline: 1.2856x; 1.2856x over previous
#include <cuda_runtime.h>
#include <cuda_bf16.h>
#include <cstdint>

#define N_NODES  50000
#define N_EDGES  800000
#define E_TOT    (N_EDGES + N_NODES)   // 850000 (edges + self loops)
#define HIDDEN   128
#define N_GRAPHS 512
#define NCHUNK   ((N_NODES + 255) / 256)   // 196

// W^T slab offsets (elements): L0 = 2*128*64, L1/L2 = 2*128*128
#define WT_OFF0  0
#define WT_OFF1  16384
#define WT_OFF2  49152
#define WT_TOT   81920

// ---------------- scratch (static device memory; no allocs) ----------------
__device__ float g_xl[(size_t)N_NODES * HIDDEN];
__device__ float g_xr[(size_t)N_NODES * HIDDEN];
// bf16 hi/lo splits of activations (uint4-typed for 16B alignment)
__device__ uint4 g_ahi_raw[(size_t)N_NODES * HIDDEN / 8];
__device__ uint4 g_alo_raw[(size_t)N_NODES * HIDDEN / 8];
// bf16 hi/lo splits of W^T for all 3 layers, [layer][y][n][k]
__device__ uint4 g_wth_raw[WT_TOT / 8];
__device__ uint4 g_wtl_raw[WT_TOT / 8];
__device__ int   g_cnt[N_NODES];
__device__ int   g_tmp[N_NODES];
__device__ int   g_off[N_NODES + 1];
__device__ int   g_cursor[N_NODES];
__device__ int   g_srcs[E_TOT];
__device__ int   g_chunksum[NCHUNK];
__device__ int   g_chunkoff[NCHUNK];
__device__ float g_gsum[N_GRAPHS * HIDDEN];
__device__ float g_gcnt[N_GRAPHS];
__device__ int   g_is64_ei;
__device__ int   g_is64_batch;

// ---------------- dtype detection ----------------
__global__ void k_detect(const int* __restrict__ ei_raw,
                         const int* __restrict__ batch_raw) {
    if (blockIdx.x == 0 && threadIdx.x == 0) {
        int nz = 0;
        for (int i = 0; i < 64; ++i) nz |= ei_raw[2 * (i * 12000) + 1];
        g_is64_ei = (nz == 0) ? 1 : 0;
        int nzb = 0;
        for (int i = 0; i < 64; ++i) nzb |= batch_raw[2 * (i * 390) + 1];
        g_is64_batch = (nzb == 0) ? 1 : 0;
    }
}

__device__ __forceinline__ int load_idx(const void* p, long long i, int is64) {
    return is64 ? (int)((const long long*)p)[i] : ((const int*)p)[i];
}
__device__ __forceinline__ int clampi(int v, int lo, int hi) {
    return v < lo ? lo : (v > hi ? hi : v);
}

// ---------------- zero counters + pool accumulators ----------------
__global__ void k_zero() {
    int i = blockIdx.x * blockDim.x + threadIdx.x;
    if (i < N_NODES) g_cnt[i] = 0;
    if (i < N_GRAPHS * HIDDEN) g_gsum[i] = 0.f;
    if (i < N_GRAPHS) g_gcnt[i] = 0.f;
}

// ---------------- CSR build ----------------
__global__ void k_count(const void* __restrict__ ei) {
    int e = blockIdx.x * blockDim.x + threadIdx.x;
    if (e >= E_TOT) return;
    int is64 = g_is64_ei;
    int dst = (e < N_EDGES) ? load_idx(ei, (long long)N_EDGES + e, is64)
                            : (e - N_EDGES);
    dst = clampi(dst, 0, N_NODES - 1);
    atomicAdd(&g_cnt[dst], 1);
}

__global__ void k_scan1() {
    __shared__ int sm[256];
    int i = blockIdx.x * 256 + threadIdx.x;
    int v = (i < N_NODES) ? g_cnt[i] : 0;
    sm[threadIdx.x] = v;
    __syncthreads();
    #pragma unroll
    for (int d = 1; d < 256; d <<= 1) {
        int t = (threadIdx.x >= d) ? sm[threadIdx.x - d] : 0;
        __syncthreads();
        sm[threadIdx.x] += t;
        __syncthreads();
    }
    if (i < N_NODES) g_tmp[i] = sm[threadIdx.x];
    if (threadIdx.x == 255) g_chunksum[blockIdx.x] = sm[255];
}

__global__ void k_scan2() {
    __shared__ int sm[256];
    int t = threadIdx.x;
    int v = (t < NCHUNK) ? g_chunksum[t] : 0;
    sm[t] = v;
    __syncthreads();
    #pragma unroll
    for (int d = 1; d < 256; d <<= 1) {
        int u = (t >= d) ? sm[t - d] : 0;
        __syncthreads();
        sm[t] += u;
        __syncthreads();
    }
    if (t < NCHUNK) g_chunkoff[t] = sm[t] - v;
}

__global__ void k_scan3() {
    int i = blockIdx.x * 256 + threadIdx.x;
    if (i < N_NODES) {
        int v = g_tmp[i] + g_chunkoff[blockIdx.x];
        g_off[i + 1]  = v;
        g_cursor[i]   = v - g_cnt[i];
    }
    if (i == 0) g_off[0] = 0;
}

__global__ void k_scatter(const void* __restrict__ ei) {
    int e = blockIdx.x * blockDim.x + threadIdx.x;
    if (e >= E_TOT) return;
    int is64 = g_is64_ei;
    int src, dst;
    if (e < N_EDGES) {
        src = load_idx(ei, e, is64);
        dst = load_idx(ei, (long long)N_EDGES + e, is64);
    } else {
        src = e - N_EDGES; dst = src;
    }
    src = clampi(src, 0, N_NODES - 1);
    dst = clampi(dst, 0, N_NODES - 1);
    int slot = atomicAdd(&g_cursor[dst], 1);
    if (slot >= 0 && slot < E_TOT) g_srcs[slot] = src;
}

// ---------------- bf16 hi/lo split helpers ----------------
__device__ __forceinline__ void split2(float v, unsigned short& h, unsigned short& l) {
    __nv_bfloat16 hb = __float2bfloat16(v);
    float r = v - __bfloat162float(hb);
    __nv_bfloat16 lb = __float2bfloat16(r);
    h = *(unsigned short*)&hb;
    l = *(unsigned short*)&lb;
}

// split input x [N,64] into g_ahi/g_alo
__global__ void k_split_x(const float* __restrict__ x) {
    int i4 = blockIdx.x * blockDim.x + threadIdx.x;   // float4 index
    if (i4 >= N_NODES * 64 / 4) return;
    float4 v = ((const float4*)x)[i4];
    ushort4 h, l;
    split2(v.x, h.x, l.x); split2(v.y, h.y, l.y);
    split2(v.z, h.z, l.z); split2(v.w, h.w, l.w);
    ((ushort4*)g_ahi_raw)[i4] = h;
    ((ushort4*)g_alo_raw)[i4] = l;
}

// split + transpose all W matrices: g_wt*[layer][y][n][k] = split(W[y][k][n])
__global__ void k_prep_w(const float* __restrict__ Wl0, const float* __restrict__ Wr0,
                         const float* __restrict__ Wl1, const float* __restrict__ Wr1,
                         const float* __restrict__ Wl2, const float* __restrict__ Wr2) {
    int i = blockIdx.x * blockDim.x + threadIdx.x;
    if (i >= WT_TOT) return;
    int K, j; const float* W;
    if (i < WT_OFF1)      { K = 64;  j = i;            W = (j < 128*64)  ? Wl0 : Wr0; j %= 128*64; }
    else if (i < WT_OFF2) { K = 128; j = i - WT_OFF1;  W = (j < 128*128) ? Wl1 : Wr1; j %= 128*128; }
    else                  { K = 128; j = i - WT_OFF2;  W = (j < 128*128) ? Wl2 : Wr2; j %= 128*128; }
    int n = j / K, k = j % K;
    unsigned short h, l;
    split2(W[k * HIDDEN + n], h, l);
    ((unsigned short*)g_wth_raw)[i] = h;
    ((unsigned short*)g_wtl_raw)[i] = l;
}

// ---------------- tensor-core GEMM: out = (Ah+Al) @ (Wh+Wl)^T(-ish) + b ----------------
__device__ __forceinline__ void mma16816(float (&c)[4], uint32_t a0, uint32_t a1,
                                         uint32_t a2, uint32_t a3,
                                         uint32_t b0, uint32_t b1) {
    asm volatile(
        "mma.sync.aligned.m16n8k16.row.col.f32.bf16.bf16.f32 "
        "{%0,%1,%2,%3}, {%4,%5,%6,%7}, {%8,%9}, {%0,%1,%2,%3};"
        : "+f"(c[0]), "+f"(c[1]), "+f"(c[2]), "+f"(c[3])
        : "r"(a0), "r"(a1), "r"(a2), "r"(a3), "r"(b0), "r"(b1));
}

#define AW 72   // A smem row stride in bf16 (64 + 8 pad -> conflict-free frag LDS)

__global__ __launch_bounds__(256) void k_gemm_tc(
    int K, int wt_base,
    const float* __restrict__ bl, const float* __restrict__ br)
{
    extern __shared__ __align__(16) char smraw[];
    __nv_bfloat16* sAh = (__nv_bfloat16*)smraw;
    __nv_bfloat16* sAl = sAh + 128 * AW;
    __nv_bfloat16* sWh = sAl + 128 * AW;
    const int WW = K + 8;
    __nv_bfloat16* sWl = sWh + 128 * WW;

    const __nv_bfloat16* ahi = (const __nv_bfloat16*)g_ahi_raw;
    const __nv_bfloat16* alo = (const __nv_bfloat16*)g_alo_raw;
    const __nv_bfloat16* Wh  = (const __nv_bfloat16*)g_wth_raw + wt_base + blockIdx.y * 128 * K;
    const __nv_bfloat16* Wlo = (const __nv_bfloat16*)g_wtl_raw + wt_base + blockIdx.y * 128 * K;

    int t = threadIdx.x;
    int lane = t & 31, warp = t >> 5;
    int wm = warp & 3, wn = warp >> 2;
    int row0 = blockIdx.x * 128;

    // stage full W^T (both splits), padded rows
    {
        int kun = K >> 3;                       // 16B units per row
        for (int u = t; u < 128 * kun; u += 256) {
            int n = u / kun, kc = (u % kun) << 3;
            *(uint4*)&sWh[n * WW + kc] = *(const uint4*)&Wh[n * K + kc];
            *(uint4*)&sWl[n * WW + kc] = *(const uint4*)&Wlo[n * K + kc];
        }
    }

    float acc[2][8][4];
    #pragma unroll
    for (int a = 0; a < 2; ++a)
        #pragma unroll
        for (int b = 0; b < 8; ++b)
            #pragma unroll
            for (int c = 0; c < 4; ++c) acc[a][b][c] = 0.f;

    for (int k0 = 0; k0 < K; k0 += 64) {
        __syncthreads();                        // W staged / prev chunk consumed
        for (int u = t; u < 1024; u += 256) {   // A chunk: 128 rows x 64 bf16, both splits
            int r = u >> 3, kc = (u & 7) << 3;
            int grow = row0 + r;
            uint4 vh = make_uint4(0, 0, 0, 0), vl = make_uint4(0, 0, 0, 0);
            if (grow < N_NODES) {
                vh = *(const uint4*)&ahi[(size_t)grow * K + k0 + kc];
                vl = *(const uint4*)&alo[(size_t)grow * K + k0 + kc];
            }
            *(uint4*)&sAh[r * AW + kc] = vh;
            *(uint4*)&sAl[r * AW + kc] = vl;
        }
        __syncthreads();

        #pragma unroll
        for (int kk = 0; kk < 4; ++kk) {
            uint32_t ah[2][4], al[2][4];
            int ac = kk * 16 + (lane & 3) * 2;
            #pragma unroll
            for (int mt = 0; mt < 2; ++mt) {
                int ar = wm * 32 + mt * 16 + (lane >> 2);
                int base = ar * AW + ac;
                ah[mt][0] = *(const uint32_t*)&sAh[base];
                ah[mt][1] = *(const uint32_t*)&sAh[base + 8 * AW];
                ah[mt][2] = *(const uint32_t*)&sAh[base + 8];
                ah[mt][3] = *(const uint32_t*)&sAh[base + 8 * AW + 8];
                al[mt][0] = *(const uint32_t*)&sAl[base];
                al[mt][1] = *(const uint32_t*)&sAl[base + 8 * AW];
                al[mt][2] = *(const uint32_t*)&sAl[base + 8];
                al[mt][3] = *(const uint32_t*)&sAl[base + 8 * AW + 8];
            }
            #pragma unroll
            for (int nt = 0; nt < 8; ++nt) {
                int brow = wn * 64 + nt * 8 + (lane >> 2);
                int bc = k0 + kk * 16 + (lane & 3) * 2;
                int bbase = brow * WW + bc;
                uint32_t bh0 = *(const uint32_t*)&sWh[bbase];
                uint32_t bh1 = *(const uint32_t*)&sWh[bbase + 8];
                uint32_t bl0 = *(const uint32_t*)&sWl[bbase];
                uint32_t bl1 = *(const uint32_t*)&sWl[bbase + 8];
                #pragma unroll
                for (int mt = 0; mt < 2; ++mt) {
                    mma16816(acc[mt][nt], ah[mt][0], ah[mt][1], ah[mt][2], ah[mt][3], bh0, bh1);
                    mma16816(acc[mt][nt], ah[mt][0], ah[mt][1], ah[mt][2], ah[mt][3], bl0, bl1);
                    mma16816(acc[mt][nt], al[mt][0], al[mt][1], al[mt][2], al[mt][3], bh0, bh1);
                }
            }
        }
    }

    const float* bias = blockIdx.y ? br : bl;
    float* out = blockIdx.y ? g_xr : g_xl;
    #pragma unroll
    for (int nt = 0; nt < 8; ++nt) {
        int col = wn * 64 + nt * 8 + (lane & 3) * 2;
        float b0 = bias[col], b1 = bias[col + 1];
        #pragma unroll
        for (int mt = 0; mt < 2; ++mt) {
            int r = row0 + wm * 32 + mt * 16 + (lane >> 2);
            if (r < N_NODES) {
                float2 v = make_float2(acc[mt][nt][0] + b0, acc[mt][nt][1] + b1);
                *(float2*)&out[(size_t)r * HIDDEN + col] = v;
            }
            if (r + 8 < N_NODES) {
                float2 v = make_float2(acc[mt][nt][2] + b0, acc[mt][nt][3] + b1);
                *(float2*)&out[(size_t)(r + 8) * HIDDEN + col] = v;
            }
        }
    }
}

// ---------------- edge phase: warp-per-dst online softmax + aggregate ----------------
__device__ __forceinline__ float lrelu(float v) { return v > 0.f ? v : 0.2f * v; }

// mode 0: write bf16 hi/lo splits (feeds next layer's GEMM)
// mode 1: fused global mean-pool accumulation (last layer)
__global__ __launch_bounds__(256) void k_edge(const float* __restrict__ att,
                                              const float* __restrict__ bias,
                                              int mode, const void* __restrict__ batch)
{
    int warp = (blockIdx.x * blockDim.x + threadIdx.x) >> 5;
    int lane = threadIdx.x & 31;
    if (warp >= N_NODES) return;

    const float4* xl4 = (const float4*)g_xl;
    float4 a4 = ((const float4*)att)[lane];
    float4 r4 = ((const float4*)g_xr)[(size_t)warp * 32 + lane];

    int beg = g_off[warp], end = g_off[warp + 1];
    float  m = -1e30f, s = 0.f;
    float4 acc = make_float4(0.f, 0.f, 0.f, 0.f);

    for (int p = beg; p < end; ++p) {
        int src = g_srcs[p];
        float4 v = xl4[(size_t)src * 32 + lane];
        float e = lrelu(v.x + r4.x) * a4.x
                + lrelu(v.y + r4.y) * a4.y
                + lrelu(v.z + r4.z) * a4.z
                + lrelu(v.w + r4.w) * a4.w;
        #pragma unroll
        for (int o = 16; o; o >>= 1) e += __shfl_xor_sync(0xffffffffu, e, o);

        if (e <= m) {
            float q = __expf(e - m);
            s += q;
            acc.x = fmaf(q, v.x, acc.x);
            acc.y = fmaf(q, v.y, acc.y);
            acc.z = fmaf(q, v.z, acc.z);
            acc.w = fmaf(q, v.w, acc.w);
        } else {
            float c = __expf(m - e);
            s = fmaf(s, c, 1.f);
            acc.x = fmaf(acc.x, c, v.x);
            acc.y = fmaf(acc.y, c, v.y);
            acc.z = fmaf(acc.z, c, v.z);
            acc.w = fmaf(acc.w, c, v.w);
            m = e;
        }
    }

    float inv = 1.f / (s + 1e-16f);
    float4 b4 = ((const float4*)bias)[lane];
    float4 o;
    o.x = fmaxf(fmaf(acc.x, inv, b4.x), 0.f);
    o.y = fmaxf(fmaf(acc.y, inv, b4.y), 0.f);
    o.z = fmaxf(fmaf(acc.z, inv, b4.z), 0.f);
    o.w = fmaxf(fmaf(acc.w, inv, b4.w), 0.f);

    if (mode == 0) {
        ushort4 h, l;
        split2(o.x, h.x, l.x); split2(o.y, h.y, l.y);
        split2(o.z, h.z, l.z); split2(o.w, h.w, l.w);
        size_t i4 = (size_t)warp * 32 + lane;
        ((ushort4*)g_ahi_raw)[i4] = h;
        ((ushort4*)g_alo_raw)[i4] = l;
    } else {
        int g = clampi(load_idx(batch, warp, g_is64_batch), 0, N_GRAPHS - 1);
        float* base = &g_gsum[g * HIDDEN + lane * 4];
        atomicAdd(base + 0, o.x);
        atomicAdd(base + 1, o.y);
        atomicAdd(base + 2, o.z);
        atomicAdd(base + 3, o.w);
        if (lane == 0) atomicAdd(&g_gcnt[g], 1.f);
    }
}

// ---------------- head MLP ----------------
__global__ void k_final(const float* __restrict__ lin_w, const float* __restrict__ lin_b,
                        const float* __restrict__ out_w, const float* __restrict__ out_b,
                        float* __restrict__ out)
{
    int g = blockIdx.x;
    int t = threadIdx.x;          // 128 threads
    __shared__ float gm[128];
    __shared__ float hh[64];
    float cnt = fmaxf(g_gcnt[g], 1.f);
    gm[t] = g_gsum[g * HIDDEN + t] / cnt;
    __syncthreads();
    if (t < 64) {
        float acc = lin_b[t];
        #pragma unroll 8
        for (int k = 0; k < 128; ++k) acc = fmaf(gm[k], lin_w[k * 64 + t], acc);
        hh[t] = fmaxf(acc, 0.f) * out_w[t];
    }
    __syncthreads();
    if (t == 0) {
        float acc = out_b[0];
        #pragma unroll 8
        for (int k = 0; k < 64; ++k) acc += hh[k];
        out[g] = acc;
    }
}

// ---------------- launch ----------------
extern "C" void kernel_launch(void* const* d_in, const int* in_sizes, int n_in,
                              void* d_out, int out_size)
{
    const float* x     = (const float*)d_in[0];
    const void*  ei    = d_in[1];
    const void*  batch = d_in[2];
    const float* Wl[3]  = {(const float*)d_in[3],  (const float*)d_in[9],  (const float*)d_in[15]};
    const float* bl[3]  = {(const float*)d_in[4],  (const float*)d_in[10], (const float*)d_in[16]};
    const float* Wr[3]  = {(const float*)d_in[5],  (const float*)d_in[11], (const float*)d_in[17]};
    const float* br[3]  = {(const float*)d_in[6],  (const float*)d_in[12], (const float*)d_in[18]};
    const float* att[3] = {(const float*)d_in[7],  (const float*)d_in[13], (const float*)d_in[19]};
    const float* bb[3]  = {(const float*)d_in[8],  (const float*)d_in[14], (const float*)d_in[20]};
    const float* lin_w  = (const float*)d_in[21];
    const float* lin_b  = (const float*)d_in[22];
    const float* out_w  = (const float*)d_in[23];
    const float* out_b  = (const float*)d_in[24];
    float* out = (float*)d_out;

    static bool attr_set = false;
    if (!attr_set) {
        cudaFuncSetAttribute(k_gemm_tc, cudaFuncAttributeMaxDynamicSharedMemorySize,
                             (2 * 128 * AW + 2 * 128 * (128 + 8)) * 2);
        attr_set = true;
    }

    k_detect<<<1, 32>>>((const int*)ei, (const int*)batch);
    k_zero  <<<(N_GRAPHS * HIDDEN + 255) / 256, 256>>>();
    k_count <<<(E_TOT + 255) / 256, 256>>>(ei);
    k_scan1 <<<NCHUNK, 256>>>();
    k_scan2 <<<1, 256>>>();
    k_scan3 <<<NCHUNK, 256>>>();
    k_scatter<<<(E_TOT + 255) / 256, 256>>>(ei);

    k_split_x<<<(N_NODES * 16 + 255) / 256, 256>>>(x);
    k_prep_w <<<(WT_TOT + 255) / 256, 256>>>(Wl[0], Wr[0], Wl[1], Wr[1], Wl[2], Wr[2]);

    const int wt_base[3] = {WT_OFF0, WT_OFF1, WT_OFF2};
    for (int L = 0; L < 3; ++L) {
        int K = (L == 0) ? 64 : HIDDEN;
        size_t smem = (2 * 128 * AW + 2 * 128 * (K + 8)) * 2;
        dim3 grid((N_NODES + 127) / 128, 2);
        k_gemm_tc<<<grid, 256, smem>>>(K, wt_base[L], bl[L], br[L]);
        k_edge<<<(N_NODES * 32 + 255) / 256, 256>>>(att[L], bb[L], (L == 2) ? 1 : 0, batch);
    }

    k_final<<<N_GRAPHS, 128>>>(lin_w, lin_b, out_w, out_b, out);
}

// round 4
// speedup vs baseline: 1.5548x; 1.2094x over previous
#include <cuda_runtime.h>
#include <cuda_bf16.h>
#include <cstdint>

#define N_NODES  50000
#define N_EDGES  800000
#define E_TOT    (N_EDGES + N_NODES)   // 850000 (edges + self loops)
#define HIDDEN   128
#define N_GRAPHS 512
#define NCHUNK   ((N_NODES + 255) / 256)   // 196

// W^T slab offsets (elements): L0 = 2*128*64, L1/L2 = 2*128*128
#define WT_OFF0  0
#define WT_OFF1  16384
#define WT_OFF2  49152
#define WT_TOT   81920

// ---------------- scratch (static device memory; no allocs) ----------------
__device__ float g_xl[(size_t)N_NODES * HIDDEN];
__device__ float g_xr[(size_t)N_NODES * HIDDEN];
__device__ uint4 g_ahi_raw[(size_t)N_NODES * HIDDEN / 8];
__device__ uint4 g_alo_raw[(size_t)N_NODES * HIDDEN / 8];
__device__ uint4 g_wth_raw[WT_TOT / 8];
__device__ uint4 g_wtl_raw[WT_TOT / 8];
__device__ int   g_cnt[N_NODES];
__device__ int   g_tmp[N_NODES];
__device__ int   g_off[N_NODES + 1];
__device__ int   g_cursor[N_NODES];
__device__ int   g_srcs[E_TOT];
__device__ int   g_chunksum[NCHUNK];
__device__ int   g_chunkoff[NCHUNK];
__device__ float g_gsum[N_GRAPHS * HIDDEN];
__device__ float g_gcnt[N_GRAPHS];
__device__ int   g_is64_ei;
__device__ int   g_is64_batch;

__device__ __forceinline__ int load_idx(const void* p, long long i, int is64) {
    return is64 ? (int)((const long long*)p)[i] : ((const int*)p)[i];
}
__device__ __forceinline__ int clampi(int v, int lo, int hi) {
    return v < lo ? lo : (v > hi ? hi : v);
}

// ---------------- zero + dtype detect (fused) ----------------
__global__ void k_zero(const int* __restrict__ ei_raw,
                       const int* __restrict__ batch_raw) {
    int i = blockIdx.x * blockDim.x + threadIdx.x;
    if (i < N_NODES) g_cnt[i] = 0;
    if (i < N_GRAPHS * HIDDEN) g_gsum[i] = 0.f;
    if (i < N_GRAPHS) g_gcnt[i] = 0.f;
    if (i == 0) {
        int nz = 0;
        for (int j = 0; j < 64; ++j) nz |= ei_raw[2 * (j * 12000) + 1];
        g_is64_ei = (nz == 0) ? 1 : 0;
        int nzb = 0;
        for (int j = 0; j < 64; ++j) nzb |= batch_raw[2 * (j * 390) + 1];
        g_is64_batch = (nzb == 0) ? 1 : 0;
    }
}

// ---------------- CSR build ----------------
__global__ void k_count(const void* __restrict__ ei) {
    int e = blockIdx.x * blockDim.x + threadIdx.x;
    if (e >= E_TOT) return;
    int is64 = g_is64_ei;
    int dst = (e < N_EDGES) ? load_idx(ei, (long long)N_EDGES + e, is64)
                            : (e - N_EDGES);
    dst = clampi(dst, 0, N_NODES - 1);
    atomicAdd(&g_cnt[dst], 1);
}

__global__ void k_scan1() {
    __shared__ int sm[256];
    int i = blockIdx.x * 256 + threadIdx.x;
    int v = (i < N_NODES) ? g_cnt[i] : 0;
    sm[threadIdx.x] = v;
    __syncthreads();
    #pragma unroll
    for (int d = 1; d < 256; d <<= 1) {
        int t = (threadIdx.x >= d) ? sm[threadIdx.x - d] : 0;
        __syncthreads();
        sm[threadIdx.x] += t;
        __syncthreads();
    }
    if (i < N_NODES) g_tmp[i] = sm[threadIdx.x];
    if (threadIdx.x == 255) g_chunksum[blockIdx.x] = sm[255];
}

__global__ void k_scan2() {
    __shared__ int sm[256];
    int t = threadIdx.x;
    int v = (t < NCHUNK) ? g_chunksum[t] : 0;
    sm[t] = v;
    __syncthreads();
    #pragma unroll
    for (int d = 1; d < 256; d <<= 1) {
        int u = (t >= d) ? sm[t - d] : 0;
        __syncthreads();
        sm[t] += u;
        __syncthreads();
    }
    if (t < NCHUNK) g_chunkoff[t] = sm[t] - v;
}

__global__ void k_scan3() {
    int i = blockIdx.x * 256 + threadIdx.x;
    if (i < N_NODES) {
        int v = g_tmp[i] + g_chunkoff[blockIdx.x];
        g_off[i + 1]  = v;
        g_cursor[i]   = v - g_cnt[i];
    }
    if (i == 0) g_off[0] = 0;
}

__global__ void k_scatter(const void* __restrict__ ei) {
    int e = blockIdx.x * blockDim.x + threadIdx.x;
    if (e >= E_TOT) return;
    int is64 = g_is64_ei;
    int src, dst;
    if (e < N_EDGES) {
        src = load_idx(ei, e, is64);
        dst = load_idx(ei, (long long)N_EDGES + e, is64);
    } else {
        src = e - N_EDGES; dst = src;
    }
    src = clampi(src, 0, N_NODES - 1);
    dst = clampi(dst, 0, N_NODES - 1);
    int slot = atomicAdd(&g_cursor[dst], 1);
    if (slot >= 0 && slot < E_TOT) g_srcs[slot] = src;
}

// ---------------- bf16 hi/lo split ----------------
__device__ __forceinline__ void split2(float v, unsigned short& h, unsigned short& l) {
    __nv_bfloat16 hb = __float2bfloat16(v);
    float r = v - __bfloat162float(hb);
    __nv_bfloat16 lb = __float2bfloat16(r);
    h = *(unsigned short*)&hb;
    l = *(unsigned short*)&lb;
}

// fused: split x [N,64] + split/transpose all W matrices
__global__ void k_prep(const float* __restrict__ x,
                       const float* __restrict__ Wl0, const float* __restrict__ Wr0,
                       const float* __restrict__ Wl1, const float* __restrict__ Wr1,
                       const float* __restrict__ Wl2, const float* __restrict__ Wr2) {
    const int NX4 = N_NODES * 64 / 4;            // 800000 float4s of x
    int i = blockIdx.x * blockDim.x + threadIdx.x;
    if (i < NX4) {
        float4 v = ((const float4*)x)[i];
        ushort4 h, l;
        split2(v.x, h.x, l.x); split2(v.y, h.y, l.y);
        split2(v.z, h.z, l.z); split2(v.w, h.w, l.w);
        ((ushort4*)g_ahi_raw)[i] = h;
        ((ushort4*)g_alo_raw)[i] = l;
        return;
    }
    int w = i - NX4;
    if (w >= WT_TOT) return;
    int K, j; const float* W;
    if (w < WT_OFF1)      { K = 64;  j = w;           W = (j < 128*64)  ? Wl0 : Wr0; j %= 128*64; }
    else if (w < WT_OFF2) { K = 128; j = w - WT_OFF1; W = (j < 128*128) ? Wl1 : Wr1; j %= 128*128; }
    else                  { K = 128; j = w - WT_OFF2; W = (j < 128*128) ? Wl2 : Wr2; j %= 128*128; }
    int n = j / K, k = j % K;
    unsigned short h, l;
    split2(W[k * HIDDEN + n], h, l);
    ((unsigned short*)g_wth_raw)[w] = h;
    ((unsigned short*)g_wtl_raw)[w] = l;
}

// ---------------- tensor-core GEMM with ldmatrix frag loads ----------------
__device__ __forceinline__ void mma16816(float (&c)[4], const uint32_t (&a)[4],
                                         uint32_t b0, uint32_t b1) {
    asm volatile(
        "mma.sync.aligned.m16n8k16.row.col.f32.bf16.bf16.f32 "
        "{%0,%1,%2,%3}, {%4,%5,%6,%7}, {%8,%9}, {%0,%1,%2,%3};"
        : "+f"(c[0]), "+f"(c[1]), "+f"(c[2]), "+f"(c[3])
        : "r"(a[0]), "r"(a[1]), "r"(a[2]), "r"(a[3]), "r"(b0), "r"(b1));
}

__device__ __forceinline__ void ldsm_x4(uint32_t (&r)[4], uint32_t addr) {
    asm volatile("ldmatrix.sync.aligned.m8n8.x4.shared.b16 {%0,%1,%2,%3}, [%4];"
                 : "=r"(r[0]), "=r"(r[1]), "=r"(r[2]), "=r"(r[3]) : "r"(addr));
}

#define AW 72   // A smem row stride in bf16 (64-col chunk + 8 pad)

__global__ __launch_bounds__(256, 2) void k_gemm_tc(
    int K, int wt_base,
    const float* __restrict__ bl, const float* __restrict__ br)
{
    extern __shared__ __align__(16) char smraw[];
    const int WW = K + 8;
    __nv_bfloat16* sAh = (__nv_bfloat16*)smraw;
    __nv_bfloat16* sAl = sAh + 128 * AW;
    __nv_bfloat16* sWh = sAl + 128 * AW;
    __nv_bfloat16* sWl = sWh + 128 * WW;

    const __nv_bfloat16* ahi = (const __nv_bfloat16*)g_ahi_raw;
    const __nv_bfloat16* alo = (const __nv_bfloat16*)g_alo_raw;
    const __nv_bfloat16* Wh  = (const __nv_bfloat16*)g_wth_raw + wt_base + blockIdx.y * 128 * K;
    const __nv_bfloat16* Wlo = (const __nv_bfloat16*)g_wtl_raw + wt_base + blockIdx.y * 128 * K;

    int t = threadIdx.x;
    int lane = t & 31, warp = t >> 5;
    int wm = warp & 3, wn = warp >> 2;
    int row0 = blockIdx.x * 128;

    // stage W^T (both splits)
    {
        int kun = K >> 3;
        for (int u = t; u < 128 * kun; u += 256) {
            int n = u / kun, kc = (u % kun) << 3;
            *(uint4*)&sWh[n * WW + kc] = *(const uint4*)&Wh[n * K + kc];
            *(uint4*)&sWl[n * WW + kc] = *(const uint4*)&Wlo[n * K + kc];
        }
    }

    // ldmatrix per-lane source offsets
    uint32_t sAh_u = (uint32_t)__cvta_generic_to_shared(sAh);
    uint32_t sAl_u = (uint32_t)__cvta_generic_to_shared(sAl);
    uint32_t sWh_u = (uint32_t)__cvta_generic_to_shared(sWh);
    uint32_t sWl_u = (uint32_t)__cvta_generic_to_shared(sWl);
    int a_lrow = lane & 15;                 // rows 0-15 within 16x16 tile
    int a_kh   = (lane >> 4) << 3;          // lanes 16-31 -> +8 k cols
    int b_row  = ((lane >> 4) << 3) + (lane & 7);   // n row within 16-row pair
    int b_kh   = ((lane >> 3) & 1) << 3;            // +8 k cols for matrices 1,3

    float acc[2][8][4];
    #pragma unroll
    for (int a = 0; a < 2; ++a)
        #pragma unroll
        for (int b = 0; b < 8; ++b)
            #pragma unroll
            for (int c = 0; c < 4; ++c) acc[a][b][c] = 0.f;

    for (int k0 = 0; k0 < K; k0 += 64) {
        __syncthreads();
        for (int u = t; u < 1024; u += 256) {   // A chunk: 128 rows x 64 bf16, both splits
            int r = u >> 3, kc = (u & 7) << 3;
            int grow = row0 + r;
            uint4 vh = make_uint4(0, 0, 0, 0), vl = make_uint4(0, 0, 0, 0);
            if (grow < N_NODES) {
                vh = *(const uint4*)&ahi[(size_t)grow * K + k0 + kc];
                vl = *(const uint4*)&alo[(size_t)grow * K + k0 + kc];
            }
            *(uint4*)&sAh[r * AW + kc] = vh;
            *(uint4*)&sAl[r * AW + kc] = vl;
        }
        __syncthreads();

        #pragma unroll
        for (int kk = 0; kk < 4; ++kk) {
            int acol = kk * 16 + a_kh;
            uint32_t ah[2][4], al[2][4];
            #pragma unroll
            for (int mt = 0; mt < 2; ++mt) {
                uint32_t off = (uint32_t)(((wm * 32 + mt * 16 + a_lrow) * AW + acol) * 2);
                ldsm_x4(ah[mt], sAh_u + off);
                ldsm_x4(al[mt], sAl_u + off);
            }
            int bcol = k0 + kk * 16 + b_kh;
            #pragma unroll
            for (int ntp = 0; ntp < 4; ++ntp) {
                uint32_t boff = (uint32_t)(((wn * 64 + ntp * 16 + b_row) * WW + bcol) * 2);
                uint32_t bh[4], blo[4];
                ldsm_x4(bh,  sWh_u + boff);
                ldsm_x4(blo, sWl_u + boff);
                #pragma unroll
                for (int mt = 0; mt < 2; ++mt) {
                    mma16816(acc[mt][2 * ntp],     ah[mt], bh[0],  bh[1]);
                    mma16816(acc[mt][2 * ntp],     ah[mt], blo[0], blo[1]);
                    mma16816(acc[mt][2 * ntp],     al[mt], bh[0],  bh[1]);
                    mma16816(acc[mt][2 * ntp + 1], ah[mt], bh[2],  bh[3]);
                    mma16816(acc[mt][2 * ntp + 1], ah[mt], blo[2], blo[3]);
                    mma16816(acc[mt][2 * ntp + 1], al[mt], bh[2],  bh[3]);
                }
            }
        }
    }

    const float* bias = blockIdx.y ? br : bl;
    float* out = blockIdx.y ? g_xr : g_xl;
    #pragma unroll
    for (int nt = 0; nt < 8; ++nt) {
        int col = wn * 64 + nt * 8 + (lane & 3) * 2;
        float b0 = bias[col], b1 = bias[col + 1];
        #pragma unroll
        for (int mt = 0; mt < 2; ++mt) {
            int r = row0 + wm * 32 + mt * 16 + (lane >> 2);
            if (r < N_NODES) {
                float2 v = make_float2(acc[mt][nt][0] + b0, acc[mt][nt][1] + b1);
                *(float2*)&out[(size_t)r * HIDDEN + col] = v;
            }
            if (r + 8 < N_NODES) {
                float2 v = make_float2(acc[mt][nt][2] + b0, acc[mt][nt][3] + b1);
                *(float2*)&out[(size_t)(r + 8) * HIDDEN + col] = v;
            }
        }
    }
}

// ---------------- edge phase: warp-per-dst online softmax + aggregate ----------------
__device__ __forceinline__ float lrelu(float v) { return v > 0.f ? v : 0.2f * v; }

__global__ __launch_bounds__(256) void k_edge(const float* __restrict__ att,
                                              const float* __restrict__ bias,
                                              int mode, const void* __restrict__ batch)
{
    int warp = (blockIdx.x * blockDim.x + threadIdx.x) >> 5;
    int lane = threadIdx.x & 31;
    if (warp >= N_NODES) return;

    const float4* xl4 = (const float4*)g_xl;
    float4 a4 = ((const float4*)att)[lane];
    float4 r4 = ((const float4*)g_xr)[(size_t)warp * 32 + lane];

    int beg = g_off[warp], end = g_off[warp + 1];
    float  m = -1e30f, s = 0.f;
    float4 acc = make_float4(0.f, 0.f, 0.f, 0.f);

    // prefetch first edge's row so the gather overlaps the softmax chain
    float4 v_n = make_float4(0.f, 0.f, 0.f, 0.f);
    if (beg < end) v_n = xl4[(size_t)g_srcs[beg] * 32 + lane];

    for (int p = beg; p < end; ++p) {
        float4 v = v_n;
        if (p + 1 < end) v_n = xl4[(size_t)g_srcs[p + 1] * 32 + lane];

        float e = lrelu(v.x + r4.x) * a4.x
                + lrelu(v.y + r4.y) * a4.y
                + lrelu(v.z + r4.z) * a4.z
                + lrelu(v.w + r4.w) * a4.w;
        #pragma unroll
        for (int o = 16; o; o >>= 1) e += __shfl_xor_sync(0xffffffffu, e, o);

        if (e <= m) {
            float q = __expf(e - m);
            s += q;
            acc.x = fmaf(q, v.x, acc.x);
            acc.y = fmaf(q, v.y, acc.y);
            acc.z = fmaf(q, v.z, acc.z);
            acc.w = fmaf(q, v.w, acc.w);
        } else {
            float c = __expf(m - e);
            s = fmaf(s, c, 1.f);
            acc.x = fmaf(acc.x, c, v.x);
            acc.y = fmaf(acc.y, c, v.y);
            acc.z = fmaf(acc.z, c, v.z);
            acc.w = fmaf(acc.w, c, v.w);
            m = e;
        }
    }

    float inv = 1.f / (s + 1e-16f);
    float4 b4 = ((const float4*)bias)[lane];
    float4 o;
    o.x = fmaxf(fmaf(acc.x, inv, b4.x), 0.f);
    o.y = fmaxf(fmaf(acc.y, inv, b4.y), 0.f);
    o.z = fmaxf(fmaf(acc.z, inv, b4.z), 0.f);
    o.w = fmaxf(fmaf(acc.w, inv, b4.w), 0.f);

    if (mode == 0) {
        ushort4 h, l;
        split2(o.x, h.x, l.x); split2(o.y, h.y, l.y);
        split2(o.z, h.z, l.z); split2(o.w, h.w, l.w);
        size_t i4 = (size_t)warp * 32 + lane;
        ((ushort4*)g_ahi_raw)[i4] = h;
        ((ushort4*)g_alo_raw)[i4] = l;
    } else {
        int g = clampi(load_idx(batch, warp, g_is64_batch), 0, N_GRAPHS - 1);
        float* base = &g_gsum[g * HIDDEN + lane * 4];
        atomicAdd(base + 0, o.x);
        atomicAdd(base + 1, o.y);
        atomicAdd(base + 2, o.z);
        atomicAdd(base + 3, o.w);
        if (lane == 0) atomicAdd(&g_gcnt[g], 1.f);
    }
}

// ---------------- head MLP ----------------
__global__ void k_final(const float* __restrict__ lin_w, const float* __restrict__ lin_b,
                        const float* __restrict__ out_w, const float* __restrict__ out_b,
                        float* __restrict__ out)
{
    int g = blockIdx.x;
    int t = threadIdx.x;          // 128 threads
    __shared__ float gm[128];
    __shared__ float hh[64];
    float cnt = fmaxf(g_gcnt[g], 1.f);
    gm[t] = g_gsum[g * HIDDEN + t] / cnt;
    __syncthreads();
    if (t < 64) {
        float acc = lin_b[t];
        #pragma unroll 8
        for (int k = 0; k < 128; ++k) acc = fmaf(gm[k], lin_w[k * 64 + t], acc);
        hh[t] = fmaxf(acc, 0.f) * out_w[t];
    }
    __syncthreads();
    if (t == 0) {
        float acc = out_b[0];
        #pragma unroll 8
        for (int k = 0; k < 64; ++k) acc += hh[k];
        out[g] = acc;
    }
}

// ---------------- launch ----------------
extern "C" void kernel_launch(void* const* d_in, const int* in_sizes, int n_in,
                              void* d_out, int out_size)
{
    const float* x     = (const float*)d_in[0];
    const void*  ei    = d_in[1];
    const void*  batch = d_in[2];
    const float* Wl[3]  = {(const float*)d_in[3],  (const float*)d_in[9],  (const float*)d_in[15]};
    const float* bl[3]  = {(const float*)d_in[4],  (const float*)d_in[10], (const float*)d_in[16]};
    const float* Wr[3]  = {(const float*)d_in[5],  (const float*)d_in[11], (const float*)d_in[17]};
    const float* br[3]  = {(const float*)d_in[6],  (const float*)d_in[12], (const float*)d_in[18]};
    const float* att[3] = {(const float*)d_in[7],  (const float*)d_in[13], (const float*)d_in[19]};
    const float* bb[3]  = {(const float*)d_in[8],  (const float*)d_in[14], (const float*)d_in[20]};
    const float* lin_w  = (const float*)d_in[21];
    const float* lin_b  = (const float*)d_in[22];
    const float* out_w  = (const float*)d_in[23];
    const float* out_b  = (const float*)d_in[24];
    float* out = (float*)d_out;

    static bool attr_set = false;
    if (!attr_set) {
        cudaFuncSetAttribute(k_gemm_tc, cudaFuncAttributeMaxDynamicSharedMemorySize,
                             (2 * 128 * AW + 2 * 128 * (128 + 8)) * 2);
        attr_set = true;
    }

    k_zero  <<<(N_GRAPHS * HIDDEN + 255) / 256, 256>>>((const int*)ei, (const int*)batch);
    k_prep  <<<(N_NODES * 16 + WT_TOT + 255) / 256, 256>>>(x, Wl[0], Wr[0], Wl[1], Wr[1], Wl[2], Wr[2]);
    k_count <<<(E_TOT + 255) / 256, 256>>>(ei);
    k_scan1 <<<NCHUNK, 256>>>();
    k_scan2 <<<1, 256>>>();
    k_scan3 <<<NCHUNK, 256>>>();
    k_scatter<<<(E_TOT + 255) / 256, 256>>>(ei);

    const int wt_base[3] = {WT_OFF0, WT_OFF1, WT_OFF2};
    for (int L = 0; L < 3; ++L) {
        int K = (L == 0) ? 64 : HIDDEN;
        size_t smem = (2 * 128 * AW + 2 * 128 * (K + 8)) * 2;
        dim3 grid((N_NODES + 127) / 128, 2);
        k_gemm_tc<<<grid, 256, smem>>>(K, wt_base[L], bl[L], br[L]);
        k_edge<<<(N_NODES * 32 + 255) / 256, 256>>>(att[L], bb[L], (L == 2) ? 1 : 0, batch);
    }

    k_final<<<N_GRAPHS, 128>>>(lin_w, lin_b, out_w, out_b, out);
}